// round 2
// baseline (speedup 1.0000x reference)
#include <cuda_runtime.h>
#include <math.h>

#define BM 128
#define BN 128
#define BK 16
#define TM 8
#define TN 8

#define NB     8
#define LQ     2048
#define LM     2048
#define DIN    1024
#define DOUT   1024

static __device__ float g_qproj[(size_t)NB * LQ * DOUT];            // 64 MB
static __device__ float g_logits[(size_t)NB * LQ * LM];             // 128 MB

__device__ __forceinline__ float neg_mask_val() { return -1000000.0f; }

// MODE 0: C[M,N] = A[M,K] * B[N,K]^T + bias[N]          (projection)
// MODE 1: batched (z): C = A*B^T + (mask==0 ? -1e6 : 0) (logits)
// MODE 2: batched (z): C[M,N] = A[M,K] * B[K,N]         (attention output)
template<int MODE>
__global__ __launch_bounds__(256)
void gemm_kernel(const float* __restrict__ A,
                 const float* __restrict__ Bmat,
                 float* __restrict__ C,
                 const float* __restrict__ bias,
                 const int* __restrict__ mask,
                 int M, int N, int K)
{
    const int z = blockIdx.z;
    const float* Ap = A;
    const float* Bp = Bmat;
    float* Cp = C;
    if (MODE == 1) { Ap += (size_t)z * M * K; Bp += (size_t)z * N * K; Cp += (size_t)z * M * N; }
    if (MODE == 2) { Ap += (size_t)z * M * K; Bp += (size_t)z * K * N; Cp += (size_t)z * M * N; }

    __shared__ float As[BK][BM];
    __shared__ float Bs[BK][BN];

    const int tid = threadIdx.x;      // 256 threads
    const int tx = tid % 16;          // n direction
    const int ty = tid / 16;          // m direction
    const int m0 = blockIdx.y * BM;
    const int n0 = blockIdx.x * BN;

    float acc[TM][TN];
#pragma unroll
    for (int i = 0; i < TM; i++)
#pragma unroll
        for (int j = 0; j < TN; j++) acc[i][j] = 0.0f;

    for (int kt = 0; kt < K; kt += BK) {
        // ---- load A tile: 128 rows(m) x 16 cols(k), transpose into As[k][m]
#pragma unroll
        for (int l = 0; l < 2; l++) {
            int lin = tid + l * 256;
            int row = lin >> 2;          // 4 float4 per 16-float row
            int c4  = (lin & 3) * 4;
            float4 v = *reinterpret_cast<const float4*>(&Ap[(size_t)(m0 + row) * K + kt + c4]);
            As[c4 + 0][row] = v.x;
            As[c4 + 1][row] = v.y;
            As[c4 + 2][row] = v.z;
            As[c4 + 3][row] = v.w;
        }
        // ---- load B tile
        if (MODE != 2) {
            // B is [N,K] row-major (K contiguous): 128 rows(n) x 16 cols(k), transpose
#pragma unroll
            for (int l = 0; l < 2; l++) {
                int lin = tid + l * 256;
                int row = lin >> 2;
                int c4  = (lin & 3) * 4;
                float4 v = *reinterpret_cast<const float4*>(&Bp[(size_t)(n0 + row) * K + kt + c4]);
                Bs[c4 + 0][row] = v.x;
                Bs[c4 + 1][row] = v.y;
                Bs[c4 + 2][row] = v.z;
                Bs[c4 + 3][row] = v.w;
            }
        } else {
            // B is [K,N] row-major (N contiguous): 16 rows(k) x 128 cols(n), direct
#pragma unroll
            for (int l = 0; l < 2; l++) {
                int lin = tid + l * 256;
                int krow = lin >> 5;          // 32 float4 per 128-float row
                int c4   = (lin & 31) * 4;
                float4 v = *reinterpret_cast<const float4*>(&Bp[(size_t)(kt + krow) * N + n0 + c4]);
                *reinterpret_cast<float4*>(&Bs[krow][c4]) = v;
            }
        }
        __syncthreads();

#pragma unroll
        for (int k = 0; k < BK; k++) {
            float a[TM], b[TN];
            *reinterpret_cast<float4*>(&a[0]) = *reinterpret_cast<const float4*>(&As[k][ty * TM]);
            *reinterpret_cast<float4*>(&a[4]) = *reinterpret_cast<const float4*>(&As[k][ty * TM + 4]);
            *reinterpret_cast<float4*>(&b[0]) = *reinterpret_cast<const float4*>(&Bs[k][tx * TN]);
            *reinterpret_cast<float4*>(&b[4]) = *reinterpret_cast<const float4*>(&Bs[k][tx * TN + 4]);
#pragma unroll
            for (int i = 0; i < TM; i++)
#pragma unroll
                for (int j = 0; j < TN; j++)
                    acc[i][j] += a[i] * b[j];
        }
        __syncthreads();
    }

    // ---- epilogue
#pragma unroll
    for (int i = 0; i < TM; i++) {
        const int m = m0 + ty * TM + i;
#pragma unroll
        for (int jj = 0; jj < TN; jj += 4) {
            float4 v;
            float* vp = &v.x;
#pragma unroll
            for (int u = 0; u < 4; u++) {
                const int n = n0 + tx * TN + jj + u;
                float val = acc[i][jj + u];
                if (MODE == 0) val += bias[n];
                if (MODE == 1) {
                    int mv = mask[(size_t)z * M * N + (size_t)m * N + n];
                    if (mv == 0) val += neg_mask_val();
                }
                vp[u] = val;
            }
            *reinterpret_cast<float4*>(&Cp[(size_t)m * N + n0 + tx * TN + jj]) = v;
        }
    }
}

// In-place row softmax over N=2048 columns; one block (256 thr) per row.
__global__ __launch_bounds__(256)
void softmax_kernel(float* __restrict__ logits)
{
    const int N = LM;                       // 2048
    float* p = logits + (size_t)blockIdx.x * N;
    const int tid  = threadIdx.x;
    const int lane = tid & 31;
    const int warp = tid >> 5;

    float4 v0 = reinterpret_cast<const float4*>(p)[tid];
    float4 v1 = reinterpret_cast<const float4*>(p)[tid + 256];
    float x[8] = { v0.x, v0.y, v0.z, v0.w, v1.x, v1.y, v1.z, v1.w };

    __shared__ float red[32];

    // ---- max reduce
    float m = x[0];
#pragma unroll
    for (int i = 1; i < 8; i++) m = fmaxf(m, x[i]);
#pragma unroll
    for (int off = 16; off > 0; off >>= 1)
        m = fmaxf(m, __shfl_xor_sync(0xffffffffu, m, off));
    if (lane == 0) red[warp] = m;
    __syncthreads();
    if (warp == 0) {
        float t = (lane < 8) ? red[lane] : -INFINITY;
#pragma unroll
        for (int off = 4; off > 0; off >>= 1)
            t = fmaxf(t, __shfl_xor_sync(0xffffffffu, t, off));
        if (lane == 0) red[0] = t;
    }
    __syncthreads();
    const float rowmax = red[0];
    __syncthreads();

    // ---- exp + sum reduce
    float s = 0.0f;
#pragma unroll
    for (int i = 0; i < 8; i++) {
        x[i] = expf(x[i] - rowmax);
        s += x[i];
    }
#pragma unroll
    for (int off = 16; off > 0; off >>= 1)
        s += __shfl_xor_sync(0xffffffffu, s, off);
    if (lane == 0) red[warp] = s;
    __syncthreads();
    if (warp == 0) {
        float t = (lane < 8) ? red[lane] : 0.0f;
#pragma unroll
        for (int off = 4; off > 0; off >>= 1)
            t += __shfl_xor_sync(0xffffffffu, t, off);
        if (lane == 0) red[0] = t;
    }
    __syncthreads();
    const float inv = 1.0f / red[0];

    v0.x = x[0] * inv; v0.y = x[1] * inv; v0.z = x[2] * inv; v0.w = x[3] * inv;
    v1.x = x[4] * inv; v1.y = x[5] * inv; v1.z = x[6] * inv; v1.w = x[7] * inv;
    reinterpret_cast<float4*>(p)[tid]       = v0;
    reinterpret_cast<float4*>(p)[tid + 256] = v1;
}

extern "C" void kernel_launch(void* const* d_in, const int* in_sizes, int n_in,
                              void* d_out, int out_size)
{
    const float* query    = (const float*)d_in[0];   // [8,2048,1024]
    const float* memories = (const float*)d_in[1];   // [8,2048,1024]
    const int*   mask     = (const int*)  d_in[2];   // [8,2048,2048]
    const float* W        = (const float*)d_in[3];   // [1024,1024] (Dout,Din)
    const float* bias     = (const float*)d_in[4];   // [1024]
    float*       out      = (float*)d_out;           // [8,2048,1024]

    float *qproj = nullptr, *logits = nullptr;
    cudaGetSymbolAddress((void**)&qproj,  g_qproj);
    cudaGetSymbolAddress((void**)&logits, g_logits);

    dim3 thr(256);

    // 1) q = query @ W^T + b  : M=16384, N=1024, K=1024
    gemm_kernel<0><<<dim3(DOUT / BN, (NB * LQ) / BM, 1), thr>>>(
        query, W, qproj, bias, nullptr, NB * LQ, DOUT, DIN);

    // 2) logits = q @ mem^T + mask : per-batch M=2048, N=2048, K=1024
    gemm_kernel<1><<<dim3(LM / BN, LQ / BM, NB), thr>>>(
        qproj, memories, logits, nullptr, mask, LQ, LM, DOUT);

    // 3) row softmax (in place)
    softmax_kernel<<<NB * LQ, 256>>>(logits);

    // 4) out = P @ mem : per-batch M=2048, N=1024, K=2048
    gemm_kernel<2><<<dim3(DOUT / BN, LQ / BM, NB), thr>>>(
        logits, memories, out, nullptr, nullptr, LQ, DOUT, LM);
}

// round 8
// speedup vs baseline: 3.3043x; 3.3043x over previous
#include <cuda_runtime.h>
#include <cuda_bf16.h>
#include <math.h>
#include <stdint.h>

#define NB 8
#define LQ 2048
#define LM 2048
#define DIN 1024
#define DOUT 1024
#define NEGV -1000000.0f

typedef __nv_bfloat16 bf16;

// ---------------- scratch ----------------------------------------------------
static __device__ bf16 g_qhi [(size_t)NB*LQ*DIN];
static __device__ bf16 g_qlo [(size_t)NB*LQ*DIN];
static __device__ bf16 g_whi [(size_t)DOUT*DIN];
static __device__ bf16 g_wlo [(size_t)DOUT*DIN];
static __device__ bf16 g_mhi [(size_t)NB*LM*DOUT];
static __device__ bf16 g_mlo [(size_t)NB*LM*DOUT];
static __device__ bf16 g_mthi[(size_t)NB*DOUT*LM];
static __device__ bf16 g_mtlo[(size_t)NB*DOUT*LM];
static __device__ bf16 g_pjhi[(size_t)NB*LQ*DOUT];
static __device__ bf16 g_pjlo[(size_t)NB*LQ*DOUT];
static __device__ float g_logits[(size_t)NB*LQ*LM];
static __device__ bf16 g_phi [(size_t)NB*LQ*LM];
static __device__ bf16 g_plo [(size_t)NB*LQ*LM];

// ---------------- PTX helpers (all arch-generic, sm_80+) ---------------------
__device__ __forceinline__ uint32_t smem_u32(const void* p) {
    uint32_t a;
    asm("{ .reg .u64 t; cvta.to.shared.u64 t, %1; cvt.u32.u64 %0, t; }" : "=r"(a) : "l"(p));
    return a;
}
#define CP_ASYNC16(sa, gp) \
    asm volatile("cp.async.cg.shared.global [%0], [%1], 16;" :: "r"(sa), "l"(gp) : "memory")
#define CP_COMMIT() asm volatile("cp.async.commit_group;" ::: "memory")
#define CP_WAIT1()  asm volatile("cp.async.wait_group 1;" ::: "memory")
#define CP_WAIT0()  asm volatile("cp.async.wait_group 0;" ::: "memory")

__device__ __forceinline__ void ldmat4(uint32_t& r0, uint32_t& r1, uint32_t& r2, uint32_t& r3,
                                       uint32_t addr) {
    asm volatile("ldmatrix.sync.aligned.m8n8.x4.shared.b16 {%0,%1,%2,%3}, [%4];"
                 : "=r"(r0), "=r"(r1), "=r"(r2), "=r"(r3) : "r"(addr));
}
__device__ __forceinline__ void mma_bf16(float* d, const uint32_t* a, uint32_t b0, uint32_t b1) {
    asm volatile(
        "mma.sync.aligned.m16n8k16.row.col.f32.bf16.bf16.f32 "
        "{%0,%1,%2,%3}, {%4,%5,%6,%7}, {%8,%9}, {%0,%1,%2,%3};"
        : "+f"(d[0]), "+f"(d[1]), "+f"(d[2]), "+f"(d[3])
        : "r"(a[0]), "r"(a[1]), "r"(a[2]), "r"(a[3]), "r"(b0), "r"(b1));
}

// ---------------- split / transpose / softmax --------------------------------
__global__ __launch_bounds__(256) void split2_kernel(
    const float4* __restrict__ in, uint2* __restrict__ hi, uint2* __restrict__ lo, int n4)
{
    int i = blockIdx.x * 256 + threadIdx.x;
    if (i >= n4) return;
    float4 v = in[i];
    bf16 h0 = __float2bfloat16(v.x), h1 = __float2bfloat16(v.y);
    bf16 h2 = __float2bfloat16(v.z), h3 = __float2bfloat16(v.w);
    bf16 l0 = __float2bfloat16(v.x - __bfloat162float(h0));
    bf16 l1 = __float2bfloat16(v.y - __bfloat162float(h1));
    bf16 l2 = __float2bfloat16(v.z - __bfloat162float(h2));
    bf16 l3 = __float2bfloat16(v.w - __bfloat162float(h3));
    __nv_bfloat162 ha(h0, h1), hb(h2, h3), la(l0, l1), lb(l2, l3);
    uint2 hv, lv;
    hv.x = *(uint32_t*)&ha; hv.y = *(uint32_t*)&hb;
    lv.x = *(uint32_t*)&la; lv.y = *(uint32_t*)&lb;
    hi[i] = hv; lo[i] = lv;
}

__global__ __launch_bounds__(256) void tsplit_kernel(
    const float* __restrict__ in, bf16* __restrict__ thi, bf16* __restrict__ tlo)
{
    __shared__ float t[32][33];
    int b = blockIdx.z;
    int m0 = blockIdx.x * 32, d0 = blockIdx.y * 32;
    int tx = threadIdx.x, ty = threadIdx.y;      // 32 x 8
    const float* src = in + (size_t)b * LM * DOUT;
#pragma unroll
    for (int r = 0; r < 4; r++)
        t[ty + 8 * r][tx] = src[(size_t)(m0 + ty + 8 * r) * DOUT + d0 + tx];
    __syncthreads();
#pragma unroll
    for (int r = 0; r < 4; r++) {
        int d = d0 + ty + 8 * r, m = m0 + tx;
        float v = t[tx][ty + 8 * r];
        bf16 h = __float2bfloat16(v);
        bf16 l = __float2bfloat16(v - __bfloat162float(h));
        size_t o = ((size_t)b * DOUT + d) * LM + m;
        thi[o] = h; tlo[o] = l;
    }
}

__global__ __launch_bounds__(256) void softmax_kernel(
    const float* __restrict__ logits, bf16* __restrict__ phi, bf16* __restrict__ plo)
{
    const float* p = logits + (size_t)blockIdx.x * LM;
    const int tid = threadIdx.x, lane = tid & 31, warp = tid >> 5;
    float4 v0 = reinterpret_cast<const float4*>(p)[tid];
    float4 v1 = reinterpret_cast<const float4*>(p)[tid + 256];
    float x[8] = { v0.x, v0.y, v0.z, v0.w, v1.x, v1.y, v1.z, v1.w };
    __shared__ float red[32];

    float m = x[0];
#pragma unroll
    for (int i = 1; i < 8; i++) m = fmaxf(m, x[i]);
#pragma unroll
    for (int off = 16; off > 0; off >>= 1) m = fmaxf(m, __shfl_xor_sync(~0u, m, off));
    if (lane == 0) red[warp] = m;
    __syncthreads();
    if (warp == 0) {
        float t = (lane < 8) ? red[lane] : -INFINITY;
#pragma unroll
        for (int off = 4; off > 0; off >>= 1) t = fmaxf(t, __shfl_xor_sync(~0u, t, off));
        if (lane == 0) red[0] = t;
    }
    __syncthreads();
    const float rowmax = red[0];
    __syncthreads();

    float s = 0.f;
#pragma unroll
    for (int i = 0; i < 8; i++) { x[i] = expf(x[i] - rowmax); s += x[i]; }
#pragma unroll
    for (int off = 16; off > 0; off >>= 1) s += __shfl_xor_sync(~0u, s, off);
    if (lane == 0) red[warp] = s;
    __syncthreads();
    if (warp == 0) {
        float t = (lane < 8) ? red[lane] : 0.f;
#pragma unroll
        for (int off = 4; off > 0; off >>= 1) t += __shfl_xor_sync(~0u, t, off);
        if (lane == 0) red[0] = t;
    }
    __syncthreads();
    const float inv = 1.0f / red[0];

    size_t base = (size_t)blockIdx.x * LM;
#pragma unroll
    for (int h = 0; h < 2; h++) {
        size_t c0 = base + (size_t)(tid + h * 256) * 4;
        float w0 = x[4*h+0] * inv, w1 = x[4*h+1] * inv, w2 = x[4*h+2] * inv, w3 = x[4*h+3] * inv;
        bf16 h0 = __float2bfloat16(w0), h1 = __float2bfloat16(w1);
        bf16 h2 = __float2bfloat16(w2), h3 = __float2bfloat16(w3);
        bf16 l0 = __float2bfloat16(w0 - __bfloat162float(h0));
        bf16 l1 = __float2bfloat16(w1 - __bfloat162float(h1));
        bf16 l2 = __float2bfloat16(w2 - __bfloat162float(h2));
        bf16 l3 = __float2bfloat16(w3 - __bfloat162float(h3));
        __nv_bfloat162 ha(h0, h1), hb(h2, h3), la(l0, l1), lb(l2, l3);
        uint2 hv, lv;
        hv.x = *(uint32_t*)&ha; hv.y = *(uint32_t*)&hb;
        lv.x = *(uint32_t*)&la; lv.y = *(uint32_t*)&lb;
        *(uint2*)(phi + c0) = hv;
        *(uint2*)(plo + c0) = lv;
    }
}

// ---------------- split-bf16 mma.sync GEMM -----------------------------------
// C[M,N] = (Ah+Al)[M,K] @ (Bh+Bl)[N,K]^T   3-pass split (hh + hl + lh), fp32 acc
// 128x128 block tile, BK=32, 8 warps (4x2), warp tile 32x64, cp.async 2-stage.
#define PITCH  80                     // bytes per 32-bf16 smem row (conflict-free)
#define TILEB  (128 * PITCH)          // 10240
#define STAGEB (4 * TILEB)            // Ah, Al, Bh, Bl
#define SMEMB  (2 * STAGEB)           // 81920

template<int MODE>
__global__ __launch_bounds__(256, 1) void gemm_mma(
    const bf16* __restrict__ Ah_, const bf16* __restrict__ Al_,
    const bf16* __restrict__ Bh_, const bf16* __restrict__ Bl_,
    float* __restrict__ Cf, bf16* __restrict__ Chi, bf16* __restrict__ Clo,
    const float* __restrict__ bias, const int* __restrict__ mask,
    int K, int Ntot, long long saz, long long sbz, long long scz)
{
    extern __shared__ __align__(128) char smem[];
    const uint32_t sb = smem_u32(smem);
    const int tid = threadIdx.x, wid = tid >> 5, lane = tid & 31;
    const int z = blockIdx.z;
    const int m0 = blockIdx.y * 128, n0 = blockIdx.x * 128;

    const bf16* Ahp = Ah_ + (size_t)saz * z;
    const bf16* Alp = Al_ + (size_t)saz * z;
    const bf16* Bhp = Bh_ + (size_t)sbz * z;
    const bf16* Blp = Bl_ + (size_t)sbz * z;

    const int NC = K >> 5;

    // per-thread load slots: v = tid + 256*j -> row v>>2, 16B chunk v&3
    const int r0v = tid >> 2, c0v = tid & 3;
    const int r1v = (tid + 256) >> 2, c1v = tid & 3;   // (tid+256)&3 == tid&3

    auto issue = [&](int i, int s) {
        const int kt = i << 5;
        const uint32_t st = sb + s * STAGEB;
        {
            uint32_t so = st + r0v * PITCH + c0v * 16;
            size_t ga = (size_t)(m0 + r0v) * K + kt + c0v * 8;
            size_t gb = (size_t)(n0 + r0v) * K + kt + c0v * 8;
            CP_ASYNC16(so + 0 * TILEB, Ahp + ga);
            CP_ASYNC16(so + 1 * TILEB, Alp + ga);
            CP_ASYNC16(so + 2 * TILEB, Bhp + gb);
            CP_ASYNC16(so + 3 * TILEB, Blp + gb);
        }
        {
            uint32_t so = st + r1v * PITCH + c1v * 16;
            size_t ga = (size_t)(m0 + r1v) * K + kt + c1v * 8;
            size_t gb = (size_t)(n0 + r1v) * K + kt + c1v * 8;
            CP_ASYNC16(so + 0 * TILEB, Ahp + ga);
            CP_ASYNC16(so + 1 * TILEB, Alp + ga);
            CP_ASYNC16(so + 2 * TILEB, Bhp + gb);
            CP_ASYNC16(so + 3 * TILEB, Blp + gb);
        }
        CP_COMMIT();
    };

    float acc[2][8][4];
#pragma unroll
    for (int a = 0; a < 2; a++)
#pragma unroll
        for (int b = 0; b < 8; b++)
#pragma unroll
            for (int c = 0; c < 4; c++) acc[a][b][c] = 0.f;

    const int wm = (wid & 3) * 32;     // warp row origin in tile
    const int wn = (wid >> 2) * 64;    // warp col origin in tile
    const int lrow = lane & 15;        // ldmatrix row lane
    const int lcol = (lane >> 4) * 16; // ldmatrix 16B half-select

    issue(0, 0);

    for (int i = 0; i < NC; i++) {
        const int s = i & 1;
        if (i + 1 < NC) { issue(i + 1, s ^ 1); CP_WAIT1(); }
        else            { CP_WAIT0(); }
        __syncthreads();

        const uint32_t st = sb + s * STAGEB;
#pragma unroll
        for (int kk = 0; kk < 2; kk++) {
            const uint32_t koff = kk * 32 + lcol;
            uint32_t aH[2][4], aL[2][4], bH[4][4], bL[4][4];
#pragma unroll
            for (int mi = 0; mi < 2; mi++) {
                uint32_t ad = st + (wm + mi * 16 + lrow) * PITCH + koff;
                ldmat4(aH[mi][0], aH[mi][1], aH[mi][2], aH[mi][3], ad);
                ldmat4(aL[mi][0], aL[mi][1], aL[mi][2], aL[mi][3], ad + TILEB);
            }
#pragma unroll
            for (int np = 0; np < 4; np++) {
                uint32_t bd = st + 2 * TILEB + (wn + np * 16 + lrow) * PITCH + koff;
                ldmat4(bH[np][0], bH[np][1], bH[np][2], bH[np][3], bd);
                ldmat4(bL[np][0], bL[np][1], bL[np][2], bL[np][3], bd + TILEB);
            }
#pragma unroll
            for (int mi = 0; mi < 2; mi++)
#pragma unroll
                for (int ni = 0; ni < 8; ni++) {
                    const int np = ni >> 1, h = ni & 1;
                    mma_bf16(acc[mi][ni], aH[mi], bH[np][h], bH[np][h + 2]);
                    mma_bf16(acc[mi][ni], aH[mi], bL[np][h], bL[np][h + 2]);
                    mma_bf16(acc[mi][ni], aL[mi], bH[np][h], bH[np][h + 2]);
                }
        }
        __syncthreads();
    }

    // ---- epilogue: rows wm+mi*16+(lane>>2)+{0,8}, cols wn+ni*8+2*(lane&3)
    const int er = lane >> 2, ec = (lane & 3) * 2;
#pragma unroll
    for (int mi = 0; mi < 2; mi++) {
#pragma unroll
        for (int h = 0; h < 2; h++) {
            const int m = m0 + wm + mi * 16 + er + h * 8;
#pragma unroll
            for (int ni = 0; ni < 8; ni++) {
                const int n = n0 + wn + ni * 8 + ec;
                float v0 = acc[mi][ni][2 * h + 0];
                float v1 = acc[mi][ni][2 * h + 1];
                if (MODE == 0) {
                    v0 += bias[n]; v1 += bias[n + 1];
                    bf16 h0 = __float2bfloat16(v0), h1 = __float2bfloat16(v1);
                    bf16 l0 = __float2bfloat16(v0 - __bfloat162float(h0));
                    bf16 l1 = __float2bfloat16(v1 - __bfloat162float(h1));
                    __nv_bfloat162 hp(h0, h1), lp(l0, l1);
                    *(uint32_t*)(Chi + (size_t)m * Ntot + n) = *(uint32_t*)&hp;
                    *(uint32_t*)(Clo + (size_t)m * Ntot + n) = *(uint32_t*)&lp;
                } else {
                    size_t co = (size_t)scz * z + (size_t)m * Ntot + n;
                    if (MODE == 1) {
                        int2 mv = *(const int2*)(mask + co);
                        if (mv.x == 0) v0 += NEGV;
                        if (mv.y == 0) v1 += NEGV;
                    }
                    float2 o; o.x = v0; o.y = v1;
                    *(float2*)(Cf + co) = o;
                }
            }
        }
    }
}

// ---------------- launch -----------------------------------------------------
extern "C" void kernel_launch(void* const* d_in, const int* in_sizes, int n_in,
                              void* d_out, int out_size)
{
    const float* query    = (const float*)d_in[0];
    const float* memories = (const float*)d_in[1];
    const int*   mask     = (const int*)  d_in[2];
    const float* W        = (const float*)d_in[3];
    const float* bias     = (const float*)d_in[4];
    float*       out      = (float*)d_out;

    bf16 *qhi, *qlo, *whi, *wlo, *mhi, *mlo, *mthi, *mtlo, *pjhi, *pjlo, *phi, *plo;
    float* logits;
    cudaGetSymbolAddress((void**)&qhi,  g_qhi);  cudaGetSymbolAddress((void**)&qlo,  g_qlo);
    cudaGetSymbolAddress((void**)&whi,  g_whi);  cudaGetSymbolAddress((void**)&wlo,  g_wlo);
    cudaGetSymbolAddress((void**)&mhi,  g_mhi);  cudaGetSymbolAddress((void**)&mlo,  g_mlo);
    cudaGetSymbolAddress((void**)&mthi, g_mthi); cudaGetSymbolAddress((void**)&mtlo, g_mtlo);
    cudaGetSymbolAddress((void**)&pjhi, g_pjhi); cudaGetSymbolAddress((void**)&pjlo, g_pjlo);
    cudaGetSymbolAddress((void**)&phi,  g_phi);  cudaGetSymbolAddress((void**)&plo,  g_plo);
    cudaGetSymbolAddress((void**)&logits, g_logits);

    cudaFuncSetAttribute(gemm_mma<0>, cudaFuncAttributeMaxDynamicSharedMemorySize, SMEMB);
    cudaFuncSetAttribute(gemm_mma<1>, cudaFuncAttributeMaxDynamicSharedMemorySize, SMEMB);
    cudaFuncSetAttribute(gemm_mma<2>, cudaFuncAttributeMaxDynamicSharedMemorySize, SMEMB);

    int n4q = NB * LQ * DIN / 4;
    split2_kernel<<<n4q / 256, 256>>>((const float4*)query, (uint2*)qhi, (uint2*)qlo, n4q);
    int n4w = DOUT * DIN / 4;
    split2_kernel<<<n4w / 256, 256>>>((const float4*)W, (uint2*)whi, (uint2*)wlo, n4w);
    int n4m = NB * LM * DOUT / 4;
    split2_kernel<<<n4m / 256, 256>>>((const float4*)memories, (uint2*)mhi, (uint2*)mlo, n4m);
    tsplit_kernel<<<dim3(LM / 32, DOUT / 32, NB), dim3(32, 8)>>>(memories, mthi, mtlo);

    // 1) qproj = query @ W^T + b  (M=16384, N=1024, K=1024) -> split bf16
    gemm_mma<0><<<dim3(DOUT / 128, (NB * LQ) / 128, 1), 256, SMEMB>>>(
        qhi, qlo, whi, wlo, nullptr, pjhi, pjlo, bias, nullptr,
        DIN, DOUT, 0, 0, 0);

    // 2) logits = qproj @ mem^T + mask  (per-batch 2048x2048, K=1024)
    gemm_mma<1><<<dim3(LM / 128, LQ / 128, NB), 256, SMEMB>>>(
        pjhi, pjlo, mhi, mlo, logits, nullptr, nullptr, nullptr, mask,
        DOUT, LM, (long long)LQ * DOUT, (long long)LM * DOUT, (long long)LQ * LM);

    // 3) softmax -> split bf16 P
    softmax_kernel<<<NB * LQ, 256>>>(logits, phi, plo);

    // 4) out = P @ memT^T  (per-batch 2048x1024, K=2048)
    gemm_mma<2><<<dim3(DOUT / 128, LQ / 128, NB), 256, SMEMB>>>(
        phi, plo, mthi, mtlo, out, nullptr, nullptr, nullptr, nullptr,
        LM, DOUT, (long long)LQ * LM, (long long)DOUT * LM, (long long)LQ * DOUT);
}